// round 9
// baseline (speedup 1.0000x reference)
#include <cuda_runtime.h>
#include <cuda_bf16.h>
#include <cuda_fp16.h>
#include <math.h>

#define NMAX 100000
#define EMAX 1600000
#define FDIM 128
#define FFDIM 512

// ---------------- scratch (static device globals; no allocation) ----------------
__device__ __half s_xlh[(size_t)NMAX * FDIM]; // source-side transform, fp16 (gathered)
__device__ float s_xr [(size_t)NMAX * FDIM];  // target-side transform, fp32
__device__ float s_h  [(size_t)NMAX * FDIM];  // GAT output (+bias), residual stream
__device__ float s_t  [(size_t)NMAX * FDIM];  // LN1 output
__device__ float s_u  [(size_t)NMAX * FFDIM]; // silu(t@W1+b)
__device__ float s_wcat[FDIM * 256];          // [Wl | Wr] concatenated along cols
__device__ float s_bcat[256];

// CSR build scratch
__device__ int s_deg [NMAX];
__device__ int s_off [NMAX];
__device__ int s_cur [NMAX];
__device__ int s_inc [NMAX];
__device__ int s_bsum[1024];
__device__ int s_srcs[EMAX];

// ---------------- weight concat prep + degree histogram (merged) ----------------
__global__ void kz_prep_hist(const float* __restrict__ Wl, const float* __restrict__ Wr,
                             const float* __restrict__ bl, const float* __restrict__ br,
                             const int* __restrict__ ei, int E_) {
    int i = blockIdx.x * blockDim.x + threadIdx.x;
    if (i < FDIM * 256) {
        int k = i >> 8, j = i & 255;
        s_wcat[i] = (j < 128) ? Wl[k * 128 + j] : Wr[k * 128 + (j - 128)];
    }
    if (i < 256) s_bcat[i] = (i < 128) ? bl[i] : br[i - 128];
    if (i < E_) atomicAdd(&s_deg[ei[E_ + i]], 1);
}

// ---------------- CSR scans + scatter ----------------
__global__ void kz_scan1(int n) {
    __shared__ int sm[256];
    int t = threadIdx.x;
    int idx = blockIdx.x * 256 + t;
    int v = (idx < n) ? s_deg[idx] : 0;
    sm[t] = v;
    __syncthreads();
#pragma unroll
    for (int o = 1; o < 256; o <<= 1) {
        int add = (t >= o) ? sm[t - o] : 0;
        __syncthreads();
        sm[t] += add;
        __syncthreads();
    }
    if (idx < n) s_inc[idx] = sm[t];
    if (t == 255) s_bsum[blockIdx.x] = sm[255];
}

__global__ void kz_scan2(int nblocks) {
    __shared__ int sm[1024];
    int t = threadIdx.x;
    sm[t] = (t < nblocks) ? s_bsum[t] : 0;
    __syncthreads();
#pragma unroll
    for (int o = 1; o < 1024; o <<= 1) {
        int add = (t >= o) ? sm[t - o] : 0;
        __syncthreads();
        sm[t] += add;
        __syncthreads();
    }
    if (t < nblocks) s_bsum[t] = sm[t];
}

__global__ void kz_scan3(int n) {
    int idx = blockIdx.x * blockDim.x + threadIdx.x;
    if (idx >= n) return;
    int b = idx >> 8;
    int prev = (b > 0) ? s_bsum[b - 1] : 0;
    int excl = s_inc[idx] - s_deg[idx] + prev;
    s_off[idx] = excl;
    s_cur[idx] = excl;
}

__global__ void kz_scatter(const int* __restrict__ ei, int E_) {
    int i = blockIdx.x * blockDim.x + threadIdx.x;
    if (i >= E_) return;
    int dst = ei[E_ + i];
    int pos = atomicAdd(&s_cur[dst], 1);
    s_srcs[pos] = ei[i];
}

// ---------------- fused GAT gather + LayerNorm1 (fp16 xl reads) ----------------
// one warp per node; lane covers 4 channels; head = lane>>2
__global__ void __launch_bounds__(256)
kz_gather_ln(const float* __restrict__ att, const float* __restrict__ bias,
             const float* __restrict__ g1, const float* __restrict__ bn1, int n) {
    int warp = (blockIdx.x * blockDim.x + threadIdx.x) >> 5;
    int lane = threadIdx.x & 31;
    if (warp >= n) return;

    const uint2* xlh = (const uint2*)s_xlh;   // 4 halfs per uint2
    float4 xr = ((const float4*)s_xr)[(size_t)warp * 32 + lane];
    float4 w  = ((const float4*)att)[lane];

    int start = s_off[warp];
    int deg   = s_deg[warp];

    float4 ws = make_float4(0.f, 0.f, 0.f, 0.f);
    float den = 0.f;

#define EDGE_STEP(u)                                                           \
    {                                                                          \
        float2 f0 = __half22float2(*(const __half2*)&(u).x);                   \
        float2 f1 = __half22float2(*(const __half2*)&(u).y);                   \
        float4 a = make_float4(f0.x, f0.y, f1.x, f1.y);                        \
        float4 t;                                                              \
        t.x = a.x + xr.x; t.x = t.x > 0.f ? t.x : 0.2f * t.x;                  \
        t.y = a.y + xr.y; t.y = t.y > 0.f ? t.y : 0.2f * t.y;                  \
        t.z = a.z + xr.z; t.z = t.z > 0.f ? t.z : 0.2f * t.z;                  \
        t.w = a.w + xr.w; t.w = t.w > 0.f ? t.w : 0.2f * t.w;                  \
        float p = t.x * w.x + t.y * w.y + t.z * w.z + t.w * w.w;               \
        p += __shfl_xor_sync(0xffffffffu, p, 1);                               \
        p += __shfl_xor_sync(0xffffffffu, p, 2);                               \
        float ex = __expf(p);                                                  \
        den += ex;                                                             \
        ws.x += ex * a.x; ws.y += ex * a.y;                                    \
        ws.z += ex * a.z; ws.w += ex * a.w;                                    \
    }

    int j = 0;
    for (; j + 4 <= deg; j += 4) {
        int q0 = s_srcs[start + j + 0];
        int q1 = s_srcs[start + j + 1];
        int q2 = s_srcs[start + j + 2];
        int q3 = s_srcs[start + j + 3];
        uint2 u0 = xlh[(size_t)q0 * 32 + lane];
        uint2 u1 = xlh[(size_t)q1 * 32 + lane];
        uint2 u2 = xlh[(size_t)q2 * 32 + lane];
        uint2 u3 = xlh[(size_t)q3 * 32 + lane];
        EDGE_STEP(u0) EDGE_STEP(u1) EDGE_STEP(u2) EDGE_STEP(u3)
    }
    for (; j < deg; j++) {
        int q = s_srcs[start + j];
        uint2 u = xlh[(size_t)q * 32 + lane];
        EDGE_STEP(u)
    }
#undef EDGE_STEP

    float invd = (den > 0.f) ? (1.f / den) : 0.f;
    float4 bb = ((const float4*)bias)[lane];
    float4 o;
    o.x = ws.x * invd + bb.x;
    o.y = ws.y * invd + bb.y;
    o.z = ws.z * invd + bb.z;
    o.w = ws.w * invd + bb.w;
    ((float4*)(s_h + (size_t)warp * 128))[lane] = o;

    // fused LayerNorm1 -> s_t
    float sm = o.x + o.y + o.z + o.w;
    float sq = o.x * o.x + o.y * o.y + o.z * o.z + o.w * o.w;
#pragma unroll
    for (int of = 16; of; of >>= 1) {
        sm += __shfl_xor_sync(0xffffffffu, sm, of);
        sq += __shfl_xor_sync(0xffffffffu, sq, of);
    }
    float mu = sm * (1.f / 128.f);
    float var = sq * (1.f / 128.f) - mu * mu;
    float rstd = rsqrtf(var + 1e-5f);
    float4 gg = ((const float4*)g1)[lane];
    float4 b1 = ((const float4*)bn1)[lane];
    float4 t4;
    t4.x = (o.x - mu) * rstd * gg.x + b1.x;
    t4.y = (o.y - mu) * rstd * gg.y + b1.y;
    t4.z = (o.z - mu) * rstd * gg.z + b1.z;
    t4.w = (o.w - mu) * rstd * gg.w + b1.w;
    ((float4*)(s_t + (size_t)warp * 128))[lane] = t4;
}

// ---------------- TF32 tensor-core GEMM ----------------
__device__ __forceinline__ unsigned to_tf32(float f) {
    unsigned r;
    asm("cvt.rna.tf32.f32 %0, %1;" : "=r"(r) : "f"(f));
    return r;
}

// C[M,N] = A[M,K] @ B[K,N] + bias, optional silu. BM=128, BN=128, BK=32.
// If C2 != null: bcol<128 writes PRIMARY as fp16 into Ch; bcol>=128 writes C2 (fp32).
// Otherwise writes C (fp32).
__global__ void __launch_bounds__(256, 2)
kz_mma(const float* __restrict__ A, const float* __restrict__ Bm,
       float* __restrict__ C, __half* __restrict__ Ch, float* __restrict__ C2,
       const float* __restrict__ bias,
       int M, int N, int K, int ldc, int act) {
    __shared__ unsigned As[128][36];
    __shared__ unsigned Bs[32][136];

    const int tid  = threadIdx.x;
    const int warp = tid >> 5;
    const int lane = tid & 31;
    const int wm   = (warp >> 1) * 32;
    const int wn   = (warp & 1) * 64;
    const int g    = lane >> 2;
    const int tg   = lane & 3;
    const int brow = blockIdx.y * 128;
    const int bcol = blockIdx.x * 128;

    float acc[2][8][4];
#pragma unroll
    for (int i = 0; i < 2; i++)
#pragma unroll
        for (int j = 0; j < 8; j++)
#pragma unroll
            for (int q = 0; q < 4; q++) acc[i][j][q] = 0.f;

    const int arow   = tid >> 3;
    const int acol   = (tid & 7) * 4;
    const int brow_l = tid >> 5;
    const int bcol_l = (tid & 31) * 4;

    for (int k0 = 0; k0 < K; k0 += 32) {
#pragma unroll
        for (int i = 0; i < 4; i++) {
            int r = arow + i * 32;
            int grow = brow + r;
            float4 v = (grow < M) ? *(const float4*)(A + (size_t)grow * K + k0 + acol)
                                  : make_float4(0.f, 0.f, 0.f, 0.f);
            As[r][acol + 0] = to_tf32(v.x);
            As[r][acol + 1] = to_tf32(v.y);
            As[r][acol + 2] = to_tf32(v.z);
            As[r][acol + 3] = to_tf32(v.w);
        }
#pragma unroll
        for (int i = 0; i < 4; i++) {
            int r = brow_l + i * 8;
            float4 v = *(const float4*)(Bm + (size_t)(k0 + r) * N + bcol + bcol_l);
            Bs[r][bcol_l + 0] = to_tf32(v.x);
            Bs[r][bcol_l + 1] = to_tf32(v.y);
            Bs[r][bcol_l + 2] = to_tf32(v.z);
            Bs[r][bcol_l + 3] = to_tf32(v.w);
        }
        __syncthreads();

#pragma unroll
        for (int ks = 0; ks < 4; ks++) {
            const int kk = ks * 8;
            unsigned a[2][4], b[8][2];
#pragma unroll
            for (int mt = 0; mt < 2; mt++) {
                int rm = wm + mt * 16 + g;
                a[mt][0] = As[rm][kk + tg];
                a[mt][1] = As[rm + 8][kk + tg];
                a[mt][2] = As[rm][kk + tg + 4];
                a[mt][3] = As[rm + 8][kk + tg + 4];
            }
#pragma unroll
            for (int nt = 0; nt < 8; nt++) {
                int cn = wn + nt * 8 + g;
                b[nt][0] = Bs[kk + tg][cn];
                b[nt][1] = Bs[kk + tg + 4][cn];
            }
#pragma unroll
            for (int mt = 0; mt < 2; mt++)
#pragma unroll
                for (int nt = 0; nt < 8; nt++) {
                    asm volatile(
                        "mma.sync.aligned.m16n8k8.row.col.f32.tf32.tf32.f32 "
                        "{%0,%1,%2,%3}, {%4,%5,%6,%7}, {%8,%9}, {%0,%1,%2,%3};\n"
                        : "+f"(acc[mt][nt][0]), "+f"(acc[mt][nt][1]),
                          "+f"(acc[mt][nt][2]), "+f"(acc[mt][nt][3])
                        : "r"(a[mt][0]), "r"(a[mt][1]), "r"(a[mt][2]), "r"(a[mt][3]),
                          "r"(b[nt][0]), "r"(b[nt][1]));
                }
        }
        __syncthreads();
    }

    const bool fp16_out = (C2 != nullptr) && (bcol < 128);
    float* Cf = C;
    int cb = bcol;
    if (C2 && bcol >= 128) { Cf = C2; cb = bcol - 128; }

#pragma unroll
    for (int mt = 0; mt < 2; mt++) {
        int r0 = brow + wm + mt * 16 + g;
        int r1 = r0 + 8;
#pragma unroll
        for (int nt = 0; nt < 8; nt++) {
            int cfull = bcol + wn + nt * 8 + 2 * tg;
            int c = cb + wn + nt * 8 + 2 * tg;
            float b0 = bias[cfull], b1 = bias[cfull + 1];
            float v00 = acc[mt][nt][0] + b0;
            float v01 = acc[mt][nt][1] + b1;
            float v10 = acc[mt][nt][2] + b0;
            float v11 = acc[mt][nt][3] + b1;
            if (act) {
                v00 = v00 / (1.f + __expf(-v00));
                v01 = v01 / (1.f + __expf(-v01));
                v10 = v10 / (1.f + __expf(-v10));
                v11 = v11 / (1.f + __expf(-v11));
            }
            if (fp16_out) {
                if (r0 < M) *(__half2*)(Ch + (size_t)r0 * ldc + c) = __floats2half2_rn(v00, v01);
                if (r1 < M) *(__half2*)(Ch + (size_t)r1 * ldc + c) = __floats2half2_rn(v10, v11);
            } else {
                if (r0 < M) *(float2*)(Cf + (size_t)r0 * ldc + c) = make_float2(v00, v01);
                if (r1 < M) *(float2*)(Cf + (size_t)r1 * ldc + c) = make_float2(v10, v11);
            }
        }
    }
}

// ---------------- final GEMM (u @ W2 + bW2) fused with residual + LayerNorm2 ----------------
__global__ void __launch_bounds__(256, 2)
kz_mma_ln(const float* __restrict__ A, const float* __restrict__ Bm,
          const float* __restrict__ h, float* __restrict__ Out,
          const float* __restrict__ bias,
          const float* __restrict__ g2, const float* __restrict__ bn2,
          int M, int K) {
    const int N = 128;
    __shared__ unsigned As[128][36];
    __shared__ unsigned Bs[32][136];
    __shared__ float ssum[128][2];
    __shared__ float ssq [128][2];

    const int tid  = threadIdx.x;
    const int warp = tid >> 5;
    const int lane = tid & 31;
    const int wm   = (warp >> 1) * 32;
    const int wn   = (warp & 1) * 64;
    const int g    = lane >> 2;
    const int tg   = lane & 3;
    const int brow = blockIdx.y * 128;

    float acc[2][8][4];
#pragma unroll
    for (int i = 0; i < 2; i++)
#pragma unroll
        for (int j = 0; j < 8; j++)
#pragma unroll
            for (int q = 0; q < 4; q++) acc[i][j][q] = 0.f;

    const int arow   = tid >> 3;
    const int acol   = (tid & 7) * 4;
    const int brow_l = tid >> 5;
    const int bcol_l = (tid & 31) * 4;

    for (int k0 = 0; k0 < K; k0 += 32) {
#pragma unroll
        for (int i = 0; i < 4; i++) {
            int r = arow + i * 32;
            int grow = brow + r;
            float4 v = (grow < M) ? *(const float4*)(A + (size_t)grow * K + k0 + acol)
                                  : make_float4(0.f, 0.f, 0.f, 0.f);
            As[r][acol + 0] = to_tf32(v.x);
            As[r][acol + 1] = to_tf32(v.y);
            As[r][acol + 2] = to_tf32(v.z);
            As[r][acol + 3] = to_tf32(v.w);
        }
#pragma unroll
        for (int i = 0; i < 4; i++) {
            int r = brow_l + i * 8;
            float4 v = *(const float4*)(Bm + (size_t)(k0 + r) * N + bcol_l);
            Bs[r][bcol_l + 0] = to_tf32(v.x);
            Bs[r][bcol_l + 1] = to_tf32(v.y);
            Bs[r][bcol_l + 2] = to_tf32(v.z);
            Bs[r][bcol_l + 3] = to_tf32(v.w);
        }
        __syncthreads();

#pragma unroll
        for (int ks = 0; ks < 4; ks++) {
            const int kk = ks * 8;
            unsigned a[2][4], b[8][2];
#pragma unroll
            for (int mt = 0; mt < 2; mt++) {
                int rm = wm + mt * 16 + g;
                a[mt][0] = As[rm][kk + tg];
                a[mt][1] = As[rm + 8][kk + tg];
                a[mt][2] = As[rm][kk + tg + 4];
                a[mt][3] = As[rm + 8][kk + tg + 4];
            }
#pragma unroll
            for (int nt = 0; nt < 8; nt++) {
                int cn = wn + nt * 8 + g;
                b[nt][0] = Bs[kk + tg][cn];
                b[nt][1] = Bs[kk + tg + 4][cn];
            }
#pragma unroll
            for (int mt = 0; mt < 2; mt++)
#pragma unroll
                for (int nt = 0; nt < 8; nt++) {
                    asm volatile(
                        "mma.sync.aligned.m16n8k8.row.col.f32.tf32.tf32.f32 "
                        "{%0,%1,%2,%3}, {%4,%5,%6,%7}, {%8,%9}, {%0,%1,%2,%3};\n"
                        : "+f"(acc[mt][nt][0]), "+f"(acc[mt][nt][1]),
                          "+f"(acc[mt][nt][2]), "+f"(acc[mt][nt][3])
                        : "r"(a[mt][0]), "r"(a[mt][1]), "r"(a[mt][2]), "r"(a[mt][3]),
                          "r"(b[nt][0]), "r"(b[nt][1]));
                }
        }
        __syncthreads();
    }

    // ---- epilogue: vals = acc + bias + h; per-row LN ----
    float rs[2][2] = {{0.f, 0.f}, {0.f, 0.f}};
    float rq[2][2] = {{0.f, 0.f}, {0.f, 0.f}};
#pragma unroll
    for (int mt = 0; mt < 2; mt++) {
        int r0 = brow + wm + mt * 16 + g;
        int r1 = r0 + 8;
#pragma unroll
        for (int nt = 0; nt < 8; nt++) {
            int c = wn + nt * 8 + 2 * tg;
            float b0 = bias[c], b1 = bias[c + 1];
            float v00 = acc[mt][nt][0] + b0;
            float v01 = acc[mt][nt][1] + b1;
            float v10 = acc[mt][nt][2] + b0;
            float v11 = acc[mt][nt][3] + b1;
            if (r0 < M) {
                float2 hh = *(const float2*)(h + (size_t)r0 * 128 + c);
                v00 += hh.x; v01 += hh.y;
            }
            if (r1 < M) {
                float2 hh = *(const float2*)(h + (size_t)r1 * 128 + c);
                v10 += hh.x; v11 += hh.y;
            }
            acc[mt][nt][0] = v00; acc[mt][nt][1] = v01;
            acc[mt][nt][2] = v10; acc[mt][nt][3] = v11;
            rs[mt][0] += v00 + v01;
            rq[mt][0] += v00 * v00 + v01 * v01;
            rs[mt][1] += v10 + v11;
            rq[mt][1] += v10 * v10 + v11 * v11;
        }
    }
#pragma unroll
    for (int mt = 0; mt < 2; mt++)
#pragma unroll
        for (int hf = 0; hf < 2; hf++) {
            rs[mt][hf] += __shfl_xor_sync(0xffffffffu, rs[mt][hf], 1);
            rs[mt][hf] += __shfl_xor_sync(0xffffffffu, rs[mt][hf], 2);
            rq[mt][hf] += __shfl_xor_sync(0xffffffffu, rq[mt][hf], 1);
            rq[mt][hf] += __shfl_xor_sync(0xffffffffu, rq[mt][hf], 2);
        }
    if (tg == 0) {
#pragma unroll
        for (int mt = 0; mt < 2; mt++)
#pragma unroll
            for (int hf = 0; hf < 2; hf++) {
                int rl = wm + mt * 16 + hf * 8 + g;
                ssum[rl][wn >> 6] = rs[mt][hf];
                ssq [rl][wn >> 6] = rq[mt][hf];
            }
    }
    __syncthreads();

#pragma unroll
    for (int mt = 0; mt < 2; mt++) {
#pragma unroll
        for (int hf = 0; hf < 2; hf++) {
            int rl = wm + mt * 16 + hf * 8 + g;
            int rg = brow + rl;
            if (rg >= M) continue;
            float sm = ssum[rl][0] + ssum[rl][1];
            float sq = ssq [rl][0] + ssq [rl][1];
            float mu = sm * (1.f / 128.f);
            float var = sq * (1.f / 128.f) - mu * mu;
            float rstd = rsqrtf(var + 1e-5f);
#pragma unroll
            for (int nt = 0; nt < 8; nt++) {
                int c = wn + nt * 8 + 2 * tg;
                float va = acc[mt][nt][hf * 2 + 0];
                float vb = acc[mt][nt][hf * 2 + 1];
                float o0 = (va - mu) * rstd * g2[c]     + bn2[c];
                float o1 = (vb - mu) * rstd * g2[c + 1] + bn2[c + 1];
                *(float2*)(Out + (size_t)rg * 128 + c) = make_float2(o0, o1);
            }
        }
    }
}

// ---------------- launch ----------------
extern "C" void kernel_launch(void* const* d_in, const int* in_sizes, int n_in,
                              void* d_out, int out_size) {
    const float* x        = (const float*)d_in[0];
    const int*   ei       = (const int*)  d_in[1];
    const float* Wl       = (const float*)d_in[2];
    const float* bl       = (const float*)d_in[3];
    const float* Wr       = (const float*)d_in[4];
    const float* br       = (const float*)d_in[5];
    const float* att      = (const float*)d_in[6];
    const float* bias_gat = (const float*)d_in[7];
    const float* g1       = (const float*)d_in[8];
    const float* bn1      = (const float*)d_in[9];
    const float* W1       = (const float*)d_in[10];
    const float* bW1      = (const float*)d_in[11];
    const float* W2       = (const float*)d_in[12];
    const float* bW2      = (const float*)d_in[13];
    const float* g2       = (const float*)d_in[14];
    const float* bn2      = (const float*)d_in[15];
    float* out = (float*)d_out;

    const int n = in_sizes[0] / FDIM;      // 100000
    const int E = in_sizes[1] / 2;         // 1600000

    float *p_xr, *p_t, *p_u, *p_h, *p_wcat, *p_bcat;
    __half* p_xlh;
    int *p_deg;
    cudaGetSymbolAddress((void**)&p_xlh,  s_xlh);
    cudaGetSymbolAddress((void**)&p_xr,   s_xr);
    cudaGetSymbolAddress((void**)&p_t,    s_t);
    cudaGetSymbolAddress((void**)&p_u,    s_u);
    cudaGetSymbolAddress((void**)&p_h,    s_h);
    cudaGetSymbolAddress((void**)&p_wcat, s_wcat);
    cudaGetSymbolAddress((void**)&p_bcat, s_bcat);
    cudaGetSymbolAddress((void**)&p_deg,  s_deg);

    const int scan_blocks = (n + 255) / 256;

    cudaMemsetAsync(p_deg, 0, (size_t)n * sizeof(int), 0);

    // prep + hist merged
    kz_prep_hist<<<(E + 255) / 256, 256>>>(Wl, Wr, bl, br, ei, E);
    kz_scan1<<<scan_blocks, 256>>>(n);
    kz_scan2<<<1, 1024>>>(scan_blocks);
    kz_scan3<<<scan_blocks, 256>>>(n);
    kz_scatter<<<(E + 255) / 256, 256>>>(ei, E);

    const int MB = (n + 127) / 128;

    // 1) [xl(fp16) | xr(fp32)] = x @ [Wl|Wr] + [bl|br]  (tf32, split outputs)
    kz_mma<<<dim3(2, MB), 256>>>(x, p_wcat, nullptr, p_xlh, p_xr, p_bcat, n, 256, 128, 128, 0);

    // 2) fused GAT gather (fp16 reads) + LN1
    kz_gather_ln<<<(n + 7) / 8, 256>>>(att, bias_gat, g1, bn1, n);

    // 3) u = silu(t @ W1 + bW1)  (tf32)
    kz_mma<<<dim3(4, MB), 256>>>(p_t, W1, p_u, nullptr, nullptr, bW1, n, 512, 128, 512, 1);

    // 4) out = LN2(h + u @ W2 + bW2)  (tf32, fused residual + LN)
    kz_mma_ln<<<dim3(1, MB), 256>>>(p_u, W2, p_h, out, bW2, g2, bn2, n, 512);
}

// round 10
// speedup vs baseline: 1.3882x; 1.3882x over previous
#include <cuda_runtime.h>
#include <cuda_bf16.h>
#include <math.h>

#define NMAX 100000
#define EMAX 1600000
#define FDIM 128
#define FFDIM 512

// ---------------- scratch (static device globals; no allocation) ----------------
__device__ float v10_xl [(size_t)NMAX * FDIM];  // source-side transform (gathered)
__device__ float v10_xr [(size_t)NMAX * FDIM];  // target-side transform
__device__ float v10_h  [(size_t)NMAX * FDIM];  // GAT output (+bias), residual stream
__device__ float v10_t  [(size_t)NMAX * FDIM];  // LN1 output
__device__ float v10_u  [(size_t)NMAX * FFDIM]; // silu(t@W1+b)
__device__ float v10_wcat[FDIM * 256];          // [Wl | Wr] concatenated along cols
__device__ float v10_bcat[256];

// CSR build scratch
__device__ int v10_deg [NMAX];
__device__ int v10_off [NMAX];
__device__ int v10_cur [NMAX];
__device__ int v10_inc [NMAX];
__device__ int v10_bsum[1024];
__device__ int v10_srcs[EMAX];

// ---------------- weight concat prep ----------------
__global__ void kv_prep(const float* __restrict__ Wl, const float* __restrict__ Wr,
                        const float* __restrict__ bl, const float* __restrict__ br) {
    int i = blockIdx.x * blockDim.x + threadIdx.x;
    if (i < FDIM * 256) {
        int k = i >> 8, j = i & 255;
        v10_wcat[i] = (j < 128) ? Wl[k * 128 + j] : Wr[k * 128 + (j - 128)];
    }
    if (i < 256) v10_bcat[i] = (i < 128) ? bl[i] : br[i - 128];
}

// ---------------- CSR build ----------------
__global__ void kv_hist(const int* __restrict__ ei, int E_) {
    int i = blockIdx.x * blockDim.x + threadIdx.x;
    if (i < E_) atomicAdd(&v10_deg[ei[E_ + i]], 1);
}

__global__ void kv_scan1(int n) {
    __shared__ int sm[256];
    int t = threadIdx.x;
    int idx = blockIdx.x * 256 + t;
    int v = (idx < n) ? v10_deg[idx] : 0;
    sm[t] = v;
    __syncthreads();
#pragma unroll
    for (int o = 1; o < 256; o <<= 1) {
        int add = (t >= o) ? sm[t - o] : 0;
        __syncthreads();
        sm[t] += add;
        __syncthreads();
    }
    if (idx < n) v10_inc[idx] = sm[t];
    if (t == 255) v10_bsum[blockIdx.x] = sm[255];
}

__global__ void kv_scan2(int nblocks) {
    __shared__ int sm[1024];
    int t = threadIdx.x;
    sm[t] = (t < nblocks) ? v10_bsum[t] : 0;
    __syncthreads();
#pragma unroll
    for (int o = 1; o < 1024; o <<= 1) {
        int add = (t >= o) ? sm[t - o] : 0;
        __syncthreads();
        sm[t] += add;
        __syncthreads();
    }
    if (t < nblocks) v10_bsum[t] = sm[t];
}

__global__ void kv_scan3(int n) {
    int idx = blockIdx.x * blockDim.x + threadIdx.x;
    if (idx >= n) return;
    int b = idx >> 8;
    int prev = (b > 0) ? v10_bsum[b - 1] : 0;
    int excl = v10_inc[idx] - v10_deg[idx] + prev;
    v10_off[idx] = excl;
    v10_cur[idx] = excl;
}

__global__ void kv_scatter(const int* __restrict__ ei, int E_) {
    int i = blockIdx.x * blockDim.x + threadIdx.x;
    if (i >= E_) return;
    int dst = ei[E_ + i];
    int pos = atomicAdd(&v10_cur[dst], 1);
    v10_srcs[pos] = ei[i];
}

// ---------------- fused GAT gather + LayerNorm1 ----------------
__global__ void __launch_bounds__(256)
kv_gather_ln(const float* __restrict__ att, const float* __restrict__ bias,
             const float* __restrict__ g1, const float* __restrict__ bn1, int n) {
    int warp = (blockIdx.x * blockDim.x + threadIdx.x) >> 5;
    int lane = threadIdx.x & 31;
    if (warp >= n) return;

    const float4* xl4 = (const float4*)v10_xl;
    float4 xr = ((const float4*)v10_xr)[(size_t)warp * 32 + lane];
    float4 w  = ((const float4*)att)[lane];

    int start = v10_off[warp];
    int deg   = v10_deg[warp];

    float4 ws = make_float4(0.f, 0.f, 0.f, 0.f);
    float den = 0.f;

#define EDGE_STEP(a)                                                           \
    {                                                                          \
        float4 t;                                                              \
        t.x = a.x + xr.x; t.x = t.x > 0.f ? t.x : 0.2f * t.x;                  \
        t.y = a.y + xr.y; t.y = t.y > 0.f ? t.y : 0.2f * t.y;                  \
        t.z = a.z + xr.z; t.z = t.z > 0.f ? t.z : 0.2f * t.z;                  \
        t.w = a.w + xr.w; t.w = t.w > 0.f ? t.w : 0.2f * t.w;                  \
        float p = t.x * w.x + t.y * w.y + t.z * w.z + t.w * w.w;               \
        p += __shfl_xor_sync(0xffffffffu, p, 1);                               \
        p += __shfl_xor_sync(0xffffffffu, p, 2);                               \
        float ex = __expf(p);                                                  \
        den += ex;                                                             \
        ws.x += ex * a.x; ws.y += ex * a.y;                                    \
        ws.z += ex * a.z; ws.w += ex * a.w;                                    \
    }

    int j = 0;
    for (; j + 4 <= deg; j += 4) {
        int q0 = v10_srcs[start + j + 0];
        int q1 = v10_srcs[start + j + 1];
        int q2 = v10_srcs[start + j + 2];
        int q3 = v10_srcs[start + j + 3];
        float4 a0 = xl4[(size_t)q0 * 32 + lane];
        float4 a1 = xl4[(size_t)q1 * 32 + lane];
        float4 a2 = xl4[(size_t)q2 * 32 + lane];
        float4 a3 = xl4[(size_t)q3 * 32 + lane];
        EDGE_STEP(a0) EDGE_STEP(a1) EDGE_STEP(a2) EDGE_STEP(a3)
    }
    for (; j < deg; j++) {
        int q = v10_srcs[start + j];
        float4 a = xl4[(size_t)q * 32 + lane];
        EDGE_STEP(a)
    }
#undef EDGE_STEP

    float invd = (den > 0.f) ? (1.f / den) : 0.f;
    float4 bb = ((const float4*)bias)[lane];
    float4 o;
    o.x = ws.x * invd + bb.x;
    o.y = ws.y * invd + bb.y;
    o.z = ws.z * invd + bb.z;
    o.w = ws.w * invd + bb.w;
    ((float4*)(v10_h + (size_t)warp * 128))[lane] = o;

    // fused LayerNorm1 -> v10_t
    float sm = o.x + o.y + o.z + o.w;
    float sq = o.x * o.x + o.y * o.y + o.z * o.z + o.w * o.w;
#pragma unroll
    for (int of = 16; of; of >>= 1) {
        sm += __shfl_xor_sync(0xffffffffu, sm, of);
        sq += __shfl_xor_sync(0xffffffffu, sq, of);
    }
    float mu = sm * (1.f / 128.f);
    float var = sq * (1.f / 128.f) - mu * mu;
    float rstd = rsqrtf(var + 1e-5f);
    float4 gg = ((const float4*)g1)[lane];
    float4 b1 = ((const float4*)bn1)[lane];
    float4 t4;
    t4.x = (o.x - mu) * rstd * gg.x + b1.x;
    t4.y = (o.y - mu) * rstd * gg.y + b1.y;
    t4.z = (o.z - mu) * rstd * gg.z + b1.z;
    t4.w = (o.w - mu) * rstd * gg.w + b1.w;
    ((float4*)(v10_t + (size_t)warp * 128))[lane] = t4;
}

// ---------------- TF32 tensor-core GEMM ----------------
__device__ __forceinline__ unsigned cvt_tf32(float f) {
    unsigned r;
    asm("cvt.rna.tf32.f32 %0, %1;" : "=r"(r) : "f"(f));
    return r;
}

// C[M,N] = A[M,K] @ B[K,N] + bias, optional silu. BM=128, BN=128, BK=32.
// If C2 != null: blocks with bcol>=128 write C2 at (bcol-128), row stride ldc.
__global__ void __launch_bounds__(256, 2)
kv_mma(const float* __restrict__ A, const float* __restrict__ Bm,
       float* __restrict__ C, float* __restrict__ C2,
       const float* __restrict__ bias,
       int M, int N, int K, int ldc, int act) {
    __shared__ unsigned As[128][36];
    __shared__ unsigned Bs[32][136];

    const int tid  = threadIdx.x;
    const int warp = tid >> 5;
    const int lane = tid & 31;
    const int wm   = (warp >> 1) * 32;
    const int wn   = (warp & 1) * 64;
    const int g    = lane >> 2;
    const int tg   = lane & 3;
    const int brow = blockIdx.y * 128;
    const int bcol = blockIdx.x * 128;

    float* Cb = C;
    int cb = bcol;
    if (C2 && bcol >= 128) { Cb = C2; cb = bcol - 128; }

    float acc[2][8][4];
#pragma unroll
    for (int i = 0; i < 2; i++)
#pragma unroll
        for (int j = 0; j < 8; j++)
#pragma unroll
            for (int q = 0; q < 4; q++) acc[i][j][q] = 0.f;

    const int arow   = tid >> 3;
    const int acol   = (tid & 7) * 4;
    const int brow_l = tid >> 5;
    const int bcol_l = (tid & 31) * 4;

    for (int k0 = 0; k0 < K; k0 += 32) {
#pragma unroll
        for (int i = 0; i < 4; i++) {
            int r = arow + i * 32;
            int grow = brow + r;
            float4 v = (grow < M) ? *(const float4*)(A + (size_t)grow * K + k0 + acol)
                                  : make_float4(0.f, 0.f, 0.f, 0.f);
            As[r][acol + 0] = cvt_tf32(v.x);
            As[r][acol + 1] = cvt_tf32(v.y);
            As[r][acol + 2] = cvt_tf32(v.z);
            As[r][acol + 3] = cvt_tf32(v.w);
        }
#pragma unroll
        for (int i = 0; i < 4; i++) {
            int r = brow_l + i * 8;
            float4 v = *(const float4*)(Bm + (size_t)(k0 + r) * N + bcol + bcol_l);
            Bs[r][bcol_l + 0] = cvt_tf32(v.x);
            Bs[r][bcol_l + 1] = cvt_tf32(v.y);
            Bs[r][bcol_l + 2] = cvt_tf32(v.z);
            Bs[r][bcol_l + 3] = cvt_tf32(v.w);
        }
        __syncthreads();

#pragma unroll
        for (int ks = 0; ks < 4; ks++) {
            const int kk = ks * 8;
            unsigned a[2][4], b[8][2];
#pragma unroll
            for (int mt = 0; mt < 2; mt++) {
                int rm = wm + mt * 16 + g;
                a[mt][0] = As[rm][kk + tg];
                a[mt][1] = As[rm + 8][kk + tg];
                a[mt][2] = As[rm][kk + tg + 4];
                a[mt][3] = As[rm + 8][kk + tg + 4];
            }
#pragma unroll
            for (int nt = 0; nt < 8; nt++) {
                int cn = wn + nt * 8 + g;
                b[nt][0] = Bs[kk + tg][cn];
                b[nt][1] = Bs[kk + tg + 4][cn];
            }
#pragma unroll
            for (int mt = 0; mt < 2; mt++)
#pragma unroll
                for (int nt = 0; nt < 8; nt++) {
                    asm volatile(
                        "mma.sync.aligned.m16n8k8.row.col.f32.tf32.tf32.f32 "
                        "{%0,%1,%2,%3}, {%4,%5,%6,%7}, {%8,%9}, {%0,%1,%2,%3};\n"
                        : "+f"(acc[mt][nt][0]), "+f"(acc[mt][nt][1]),
                          "+f"(acc[mt][nt][2]), "+f"(acc[mt][nt][3])
                        : "r"(a[mt][0]), "r"(a[mt][1]), "r"(a[mt][2]), "r"(a[mt][3]),
                          "r"(b[nt][0]), "r"(b[nt][1]));
                }
        }
        __syncthreads();
    }

#pragma unroll
    for (int mt = 0; mt < 2; mt++) {
        int r0 = brow + wm + mt * 16 + g;
        int r1 = r0 + 8;
#pragma unroll
        for (int nt = 0; nt < 8; nt++) {
            int cfull = bcol + wn + nt * 8 + 2 * tg;
            int c = cb + wn + nt * 8 + 2 * tg;
            float b0 = bias[cfull], b1 = bias[cfull + 1];
            float v00 = acc[mt][nt][0] + b0;
            float v01 = acc[mt][nt][1] + b1;
            float v10 = acc[mt][nt][2] + b0;
            float v11 = acc[mt][nt][3] + b1;
            if (act) {
                v00 = v00 / (1.f + __expf(-v00));
                v01 = v01 / (1.f + __expf(-v01));
                v10 = v10 / (1.f + __expf(-v10));
                v11 = v11 / (1.f + __expf(-v11));
            }
            if (r0 < M) *(float2*)(Cb + (size_t)r0 * ldc + c) = make_float2(v00, v01);
            if (r1 < M) *(float2*)(Cb + (size_t)r1 * ldc + c) = make_float2(v10, v11);
        }
    }
}

// ---------------- final GEMM (u @ W2 + bW2) fused with residual + LayerNorm2 ----------------
__global__ void __launch_bounds__(256, 2)
kv_mma_ln(const float* __restrict__ A, const float* __restrict__ Bm,
          const float* __restrict__ h, float* __restrict__ Out,
          const float* __restrict__ bias,
          const float* __restrict__ g2, const float* __restrict__ bn2,
          int M, int K) {
    const int N = 128;
    __shared__ unsigned As[128][36];
    __shared__ unsigned Bs[32][136];
    __shared__ float ssum[128][2];
    __shared__ float ssq [128][2];

    const int tid  = threadIdx.x;
    const int warp = tid >> 5;
    const int lane = tid & 31;
    const int wm   = (warp >> 1) * 32;
    const int wn   = (warp & 1) * 64;
    const int g    = lane >> 2;
    const int tg   = lane & 3;
    const int brow = blockIdx.y * 128;

    float acc[2][8][4];
#pragma unroll
    for (int i = 0; i < 2; i++)
#pragma unroll
        for (int j = 0; j < 8; j++)
#pragma unroll
            for (int q = 0; q < 4; q++) acc[i][j][q] = 0.f;

    const int arow   = tid >> 3;
    const int acol   = (tid & 7) * 4;
    const int brow_l = tid >> 5;
    const int bcol_l = (tid & 31) * 4;

    for (int k0 = 0; k0 < K; k0 += 32) {
#pragma unroll
        for (int i = 0; i < 4; i++) {
            int r = arow + i * 32;
            int grow = brow + r;
            float4 v = (grow < M) ? *(const float4*)(A + (size_t)grow * K + k0 + acol)
                                  : make_float4(0.f, 0.f, 0.f, 0.f);
            As[r][acol + 0] = cvt_tf32(v.x);
            As[r][acol + 1] = cvt_tf32(v.y);
            As[r][acol + 2] = cvt_tf32(v.z);
            As[r][acol + 3] = cvt_tf32(v.w);
        }
#pragma unroll
        for (int i = 0; i < 4; i++) {
            int r = brow_l + i * 8;
            float4 v = *(const float4*)(Bm + (size_t)(k0 + r) * N + bcol_l);
            Bs[r][bcol_l + 0] = cvt_tf32(v.x);
            Bs[r][bcol_l + 1] = cvt_tf32(v.y);
            Bs[r][bcol_l + 2] = cvt_tf32(v.z);
            Bs[r][bcol_l + 3] = cvt_tf32(v.w);
        }
        __syncthreads();

#pragma unroll
        for (int ks = 0; ks < 4; ks++) {
            const int kk = ks * 8;
            unsigned a[2][4], b[8][2];
#pragma unroll
            for (int mt = 0; mt < 2; mt++) {
                int rm = wm + mt * 16 + g;
                a[mt][0] = As[rm][kk + tg];
                a[mt][1] = As[rm + 8][kk + tg];
                a[mt][2] = As[rm][kk + tg + 4];
                a[mt][3] = As[rm + 8][kk + tg + 4];
            }
#pragma unroll
            for (int nt = 0; nt < 8; nt++) {
                int cn = wn + nt * 8 + g;
                b[nt][0] = Bs[kk + tg][cn];
                b[nt][1] = Bs[kk + tg + 4][cn];
            }
#pragma unroll
            for (int mt = 0; mt < 2; mt++)
#pragma unroll
                for (int nt = 0; nt < 8; nt++) {
                    asm volatile(
                        "mma.sync.aligned.m16n8k8.row.col.f32.tf32.tf32.f32 "
                        "{%0,%1,%2,%3}, {%4,%5,%6,%7}, {%8,%9}, {%0,%1,%2,%3};\n"
                        : "+f"(acc[mt][nt][0]), "+f"(acc[mt][nt][1]),
                          "+f"(acc[mt][nt][2]), "+f"(acc[mt][nt][3])
                        : "r"(a[mt][0]), "r"(a[mt][1]), "r"(a[mt][2]), "r"(a[mt][3]),
                          "r"(b[nt][0]), "r"(b[nt][1]));
                }
        }
        __syncthreads();
    }

    // ---- epilogue: vals = acc + bias + h; per-row LN ----
    float rs[2][2] = {{0.f, 0.f}, {0.f, 0.f}};
    float rq[2][2] = {{0.f, 0.f}, {0.f, 0.f}};
#pragma unroll
    for (int mt = 0; mt < 2; mt++) {
        int r0 = brow + wm + mt * 16 + g;
        int r1 = r0 + 8;
#pragma unroll
        for (int nt = 0; nt < 8; nt++) {
            int c = wn + nt * 8 + 2 * tg;
            float b0 = bias[c], b1 = bias[c + 1];
            float v00 = acc[mt][nt][0] + b0;
            float v01 = acc[mt][nt][1] + b1;
            float v10 = acc[mt][nt][2] + b0;
            float v11 = acc[mt][nt][3] + b1;
            if (r0 < M) {
                float2 hh = *(const float2*)(h + (size_t)r0 * 128 + c);
                v00 += hh.x; v01 += hh.y;
            }
            if (r1 < M) {
                float2 hh = *(const float2*)(h + (size_t)r1 * 128 + c);
                v10 += hh.x; v11 += hh.y;
            }
            acc[mt][nt][0] = v00; acc[mt][nt][1] = v01;
            acc[mt][nt][2] = v10; acc[mt][nt][3] = v11;
            rs[mt][0] += v00 + v01;
            rq[mt][0] += v00 * v00 + v01 * v01;
            rs[mt][1] += v10 + v11;
            rq[mt][1] += v10 * v10 + v11 * v11;
        }
    }
#pragma unroll
    for (int mt = 0; mt < 2; mt++)
#pragma unroll
        for (int hf = 0; hf < 2; hf++) {
            rs[mt][hf] += __shfl_xor_sync(0xffffffffu, rs[mt][hf], 1);
            rs[mt][hf] += __shfl_xor_sync(0xffffffffu, rs[mt][hf], 2);
            rq[mt][hf] += __shfl_xor_sync(0xffffffffu, rq[mt][hf], 1);
            rq[mt][hf] += __shfl_xor_sync(0xffffffffu, rq[mt][hf], 2);
        }
    if (tg == 0) {
#pragma unroll
        for (int mt = 0; mt < 2; mt++)
#pragma unroll
            for (int hf = 0; hf < 2; hf++) {
                int rl = wm + mt * 16 + hf * 8 + g;
                ssum[rl][wn >> 6] = rs[mt][hf];
                ssq [rl][wn >> 6] = rq[mt][hf];
            }
    }
    __syncthreads();

#pragma unroll
    for (int mt = 0; mt < 2; mt++) {
#pragma unroll
        for (int hf = 0; hf < 2; hf++) {
            int rl = wm + mt * 16 + hf * 8 + g;
            int rg = brow + rl;
            if (rg >= M) continue;
            float sm = ssum[rl][0] + ssum[rl][1];
            float sq = ssq [rl][0] + ssq [rl][1];
            float mu = sm * (1.f / 128.f);
            float var = sq * (1.f / 128.f) - mu * mu;
            float rstd = rsqrtf(var + 1e-5f);
#pragma unroll
            for (int nt = 0; nt < 8; nt++) {
                int c = wn + nt * 8 + 2 * tg;
                float va = acc[mt][nt][hf * 2 + 0];
                float vb = acc[mt][nt][hf * 2 + 1];
                float o0 = (va - mu) * rstd * g2[c]     + bn2[c];
                float o1 = (vb - mu) * rstd * g2[c + 1] + bn2[c + 1];
                *(float2*)(Out + (size_t)rg * 128 + c) = make_float2(o0, o1);
            }
        }
    }
}

// ---------------- launch ----------------
extern "C" void kernel_launch(void* const* d_in, const int* in_sizes, int n_in,
                              void* d_out, int out_size) {
    const float* x        = (const float*)d_in[0];
    const int*   ei       = (const int*)  d_in[1];
    const float* Wl       = (const float*)d_in[2];
    const float* bl       = (const float*)d_in[3];
    const float* Wr       = (const float*)d_in[4];
    const float* br       = (const float*)d_in[5];
    const float* att      = (const float*)d_in[6];
    const float* bias_gat = (const float*)d_in[7];
    const float* g1       = (const float*)d_in[8];
    const float* bn1      = (const float*)d_in[9];
    const float* W1       = (const float*)d_in[10];
    const float* bW1      = (const float*)d_in[11];
    const float* W2       = (const float*)d_in[12];
    const float* bW2      = (const float*)d_in[13];
    const float* g2       = (const float*)d_in[14];
    const float* bn2      = (const float*)d_in[15];
    float* out = (float*)d_out;

    const int n = in_sizes[0] / FDIM;      // 100000
    const int E = in_sizes[1] / 2;         // 1600000

    float *p_xl, *p_xr, *p_t, *p_u, *p_h, *p_wcat, *p_bcat;
    int *p_deg;
    cudaGetSymbolAddress((void**)&p_xl,   v10_xl);
    cudaGetSymbolAddress((void**)&p_xr,   v10_xr);
    cudaGetSymbolAddress((void**)&p_t,    v10_t);
    cudaGetSymbolAddress((void**)&p_u,    v10_u);
    cudaGetSymbolAddress((void**)&p_h,    v10_h);
    cudaGetSymbolAddress((void**)&p_wcat, v10_wcat);
    cudaGetSymbolAddress((void**)&p_bcat, v10_bcat);
    cudaGetSymbolAddress((void**)&p_deg,  v10_deg);

    const int scan_blocks = (n + 255) / 256;

    kv_prep<<<(FDIM * 256 + 255) / 256, 256>>>(Wl, Wr, bl, br);
    cudaMemsetAsync(p_deg, 0, (size_t)n * sizeof(int), 0);

    kv_hist<<<(E + 255) / 256, 256>>>(ei, E);
    kv_scan1<<<scan_blocks, 256>>>(n);
    kv_scan2<<<1, 1024>>>(scan_blocks);
    kv_scan3<<<scan_blocks, 256>>>(n);
    kv_scatter<<<(E + 255) / 256, 256>>>(ei, E);

    const int MB = (n + 127) / 128;

    // 1) [xl|xr] = x @ [Wl|Wr] + [bl|br]  (tf32, split outputs)
    kv_mma<<<dim3(2, MB), 256>>>(x, p_wcat, p_xl, p_xr, p_bcat, n, 256, 128, 128, 0);

    // 2) fused GAT gather + LN1
    kv_gather_ln<<<(n + 7) / 8, 256>>>(att, bias_gat, g1, bn1, n);

    // 3) u = silu(t @ W1 + bW1)  (tf32)
    kv_mma<<<dim3(4, MB), 256>>>(p_t, W1, p_u, nullptr, bW1, n, 512, 128, 512, 1);

    // 4) out = LN2(h + u @ W2 + bW2)  (tf32, fused residual + LN)
    kv_mma_ln<<<dim3(1, MB), 256>>>(p_u, W2, p_h, out, bW2, g2, bn2, n, 512);
}

// round 12
// speedup vs baseline: 1.4903x; 1.0736x over previous
#include <cuda_runtime.h>
#include <cuda_bf16.h>
#include <cuda_fp16.h>
#include <stdint.h>
#include <math.h>

#define NMAX 100000
#define EMAX 1600000
#define FDIM 128
#define FFDIM 512

// ---------------- scratch (static device globals; no allocation) ----------------
__device__ float kg_xl [(size_t)NMAX * FDIM];  // source-side transform (gathered)
__device__ float kg_xr [(size_t)NMAX * FDIM];  // target-side transform
__device__ float kg_h  [(size_t)NMAX * FDIM];  // GAT output (+bias), residual stream
__device__ float kg_t  [(size_t)NMAX * FDIM];  // LN1 output
__device__ float kg_u  [(size_t)NMAX * FFDIM]; // silu(t@W1+b)
__device__ float kg_wcat[FDIM * 256];          // [Wl | Wr] concatenated along cols
__device__ float kg_bcat[256];

// CSR build scratch
__device__ int kg_deg [NMAX];
__device__ int kg_off [NMAX];
__device__ int kg_cur [NMAX];
__device__ int kg_inc [NMAX];
__device__ int kg_bsum[1024];
__device__ int kg_srcs[EMAX];

// ---------------- weight concat prep ----------------
__global__ void kg_prep(const float* __restrict__ Wl, const float* __restrict__ Wr,
                        const float* __restrict__ bl, const float* __restrict__ br) {
    int i = blockIdx.x * blockDim.x + threadIdx.x;
    if (i < FDIM * 256) {
        int k = i >> 8, j = i & 255;
        kg_wcat[i] = (j < 128) ? Wl[k * 128 + j] : Wr[k * 128 + (j - 128)];
    }
    if (i < 256) kg_bcat[i] = (i < 128) ? bl[i] : br[i - 128];
}

// ---------------- CSR build ----------------
__global__ void kg_hist(const int* __restrict__ ei, int E_) {
    int i = blockIdx.x * blockDim.x + threadIdx.x;
    if (i < E_) atomicAdd(&kg_deg[ei[E_ + i]], 1);
}

__global__ void kg_scan1(int n) {
    __shared__ int sm[256];
    int t = threadIdx.x;
    int idx = blockIdx.x * 256 + t;
    int v = (idx < n) ? kg_deg[idx] : 0;
    sm[t] = v;
    __syncthreads();
#pragma unroll
    for (int o = 1; o < 256; o <<= 1) {
        int add = (t >= o) ? sm[t - o] : 0;
        __syncthreads();
        sm[t] += add;
        __syncthreads();
    }
    if (idx < n) kg_inc[idx] = sm[t];
    if (t == 255) kg_bsum[blockIdx.x] = sm[255];
}

__global__ void kg_scan2(int nblocks) {
    __shared__ int sm[1024];
    int t = threadIdx.x;
    sm[t] = (t < nblocks) ? kg_bsum[t] : 0;
    __syncthreads();
#pragma unroll
    for (int o = 1; o < 1024; o <<= 1) {
        int add = (t >= o) ? sm[t - o] : 0;
        __syncthreads();
        sm[t] += add;
        __syncthreads();
    }
    if (t < nblocks) kg_bsum[t] = sm[t];
}

__global__ void kg_scan3(int n) {
    int idx = blockIdx.x * blockDim.x + threadIdx.x;
    if (idx >= n) return;
    int b = idx >> 8;
    int prev = (b > 0) ? kg_bsum[b - 1] : 0;
    int excl = kg_inc[idx] - kg_deg[idx] + prev;
    kg_off[idx] = excl;
    kg_cur[idx] = excl;
}

__global__ void kg_scatter(const int* __restrict__ ei, int E_) {
    int i = blockIdx.x * blockDim.x + threadIdx.x;
    if (i >= E_) return;
    int dst = ei[E_ + i];
    int pos = atomicAdd(&kg_cur[dst], 1);
    kg_srcs[pos] = ei[i];
}

// ---------------- fused GAT gather + LayerNorm1 ----------------
__global__ void __launch_bounds__(256)
kg_gather_ln(const float* __restrict__ att, const float* __restrict__ bias,
             const float* __restrict__ g1, const float* __restrict__ bn1, int n) {
    int warp = (blockIdx.x * blockDim.x + threadIdx.x) >> 5;
    int lane = threadIdx.x & 31;
    if (warp >= n) return;

    const float4* xl4 = (const float4*)kg_xl;
    float4 xr = ((const float4*)kg_xr)[(size_t)warp * 32 + lane];
    float4 w  = ((const float4*)att)[lane];

    int start = kg_off[warp];
    int deg   = kg_deg[warp];

    float4 ws = make_float4(0.f, 0.f, 0.f, 0.f);
    float den = 0.f;

#define EDGE_STEP(a)                                                           \
    {                                                                          \
        float4 t;                                                              \
        t.x = a.x + xr.x; t.x = t.x > 0.f ? t.x : 0.2f * t.x;                  \
        t.y = a.y + xr.y; t.y = t.y > 0.f ? t.y : 0.2f * t.y;                  \
        t.z = a.z + xr.z; t.z = t.z > 0.f ? t.z : 0.2f * t.z;                  \
        t.w = a.w + xr.w; t.w = t.w > 0.f ? t.w : 0.2f * t.w;                  \
        float p = t.x * w.x + t.y * w.y + t.z * w.z + t.w * w.w;               \
        p += __shfl_xor_sync(0xffffffffu, p, 1);                               \
        p += __shfl_xor_sync(0xffffffffu, p, 2);                               \
        float ex = __expf(p);                                                  \
        den += ex;                                                             \
        ws.x += ex * a.x; ws.y += ex * a.y;                                    \
        ws.z += ex * a.z; ws.w += ex * a.w;                                    \
    }

    int j = 0;
    for (; j + 4 <= deg; j += 4) {
        int q0 = kg_srcs[start + j + 0];
        int q1 = kg_srcs[start + j + 1];
        int q2 = kg_srcs[start + j + 2];
        int q3 = kg_srcs[start + j + 3];
        float4 a0 = xl4[(size_t)q0 * 32 + lane];
        float4 a1 = xl4[(size_t)q1 * 32 + lane];
        float4 a2 = xl4[(size_t)q2 * 32 + lane];
        float4 a3 = xl4[(size_t)q3 * 32 + lane];
        EDGE_STEP(a0) EDGE_STEP(a1) EDGE_STEP(a2) EDGE_STEP(a3)
    }
    for (; j < deg; j++) {
        int q = kg_srcs[start + j];
        float4 a = xl4[(size_t)q * 32 + lane];
        EDGE_STEP(a)
    }
#undef EDGE_STEP

    float invd = (den > 0.f) ? (1.f / den) : 0.f;
    float4 bb = ((const float4*)bias)[lane];
    float4 o;
    o.x = ws.x * invd + bb.x;
    o.y = ws.y * invd + bb.y;
    o.z = ws.z * invd + bb.z;
    o.w = ws.w * invd + bb.w;
    ((float4*)(kg_h + (size_t)warp * 128))[lane] = o;

    // fused LayerNorm1 -> kg_t
    float sm = o.x + o.y + o.z + o.w;
    float sq = o.x * o.x + o.y * o.y + o.z * o.z + o.w * o.w;
#pragma unroll
    for (int of = 16; of; of >>= 1) {
        sm += __shfl_xor_sync(0xffffffffu, sm, of);
        sq += __shfl_xor_sync(0xffffffffu, sq, of);
    }
    float mu = sm * (1.f / 128.f);
    float var = sq * (1.f / 128.f) - mu * mu;
    float rstd = rsqrtf(var + 1e-5f);
    float4 gg = ((const float4*)g1)[lane];
    float4 b1 = ((const float4*)bn1)[lane];
    float4 t4;
    t4.x = (o.x - mu) * rstd * gg.x + b1.x;
    t4.y = (o.y - mu) * rstd * gg.y + b1.y;
    t4.z = (o.z - mu) * rstd * gg.z + b1.z;
    t4.w = (o.w - mu) * rstd * gg.w + b1.w;
    ((float4*)(kg_t + (size_t)warp * 128))[lane] = t4;
}

// ---------------- FP16 tensor-core GEMM (fp32 accumulate) ----------------
__device__ __forceinline__ unsigned smem_u32(const void* p) {
    return (unsigned)__cvta_generic_to_shared(p);
}

// C[M,N] = A[M,K] @ B[K,N] + bias, optional silu. BM=128, BN=128, BK=32.
// If C2 != null: blocks with bcol>=128 write C2 at (bcol-128), row stride ldc.
__global__ void __launch_bounds__(256, 2)
kg_mma(const float* __restrict__ A, const float* __restrict__ Bm,
       float* __restrict__ C, float* __restrict__ C2,
       const float* __restrict__ bias,
       int M, int N, int K, int ldc, int act) {
    __shared__ __half Ash[128][40];    // [m][k], pitch 40 halfs: conflict-free A-frag LDS
    __shared__ __half Bsh[32][136];    // [k][n], pitch 136 halfs: conflict-free ldmatrix

    const int tid  = threadIdx.x;
    const int warp = tid >> 5;
    const int lane = tid & 31;
    const int wm   = (warp >> 1) * 32;
    const int wn   = (warp & 1) * 64;
    const int g    = lane >> 2;
    const int tg   = lane & 3;
    const int brow = blockIdx.y * 128;
    const int bcol = blockIdx.x * 128;

    float* Cb = C;
    int cb = bcol;
    if (C2 && bcol >= 128) { Cb = C2; cb = bcol - 128; }

    float acc[2][8][4];
#pragma unroll
    for (int i = 0; i < 2; i++)
#pragma unroll
        for (int j = 0; j < 8; j++)
#pragma unroll
            for (int q = 0; q < 4; q++) acc[i][j][q] = 0.f;

    const int arow   = tid >> 3;          // 0..31
    const int acol   = (tid & 7) * 4;     // 0..28
    const int brow_l = tid >> 5;          // 0..7
    const int bcol_l = (tid & 31) * 4;    // 0..124

    const unsigned bsh_base = smem_u32(&Bsh[0][0]);
    const int klane = lane & 15;

    for (int k0 = 0; k0 < K; k0 += 32) {
#pragma unroll
        for (int i = 0; i < 4; i++) {
            int r = arow + i * 32;
            int grow = brow + r;
            float4 v = (grow < M) ? *(const float4*)(A + (size_t)grow * K + k0 + acol)
                                  : make_float4(0.f, 0.f, 0.f, 0.f);
            ((__half2*)&Ash[r][acol])[0] = __floats2half2_rn(v.x, v.y);
            ((__half2*)&Ash[r][acol])[1] = __floats2half2_rn(v.z, v.w);
        }
#pragma unroll
        for (int i = 0; i < 4; i++) {
            int r = brow_l + i * 8;
            float4 v = *(const float4*)(Bm + (size_t)(k0 + r) * N + bcol + bcol_l);
            ((__half2*)&Bsh[r][bcol_l])[0] = __floats2half2_rn(v.x, v.y);
            ((__half2*)&Bsh[r][bcol_l])[1] = __floats2half2_rn(v.z, v.w);
        }
        __syncthreads();

#pragma unroll
        for (int ks = 0; ks < 2; ks++) {
            const int kk = ks * 16;
            unsigned a[2][4], b[8][2];
#pragma unroll
            for (int mt = 0; mt < 2; mt++) {
                int rm = wm + mt * 16 + g;
                a[mt][0] = *(const unsigned*)&Ash[rm    ][kk + 2 * tg];
                a[mt][1] = *(const unsigned*)&Ash[rm + 8][kk + 2 * tg];
                a[mt][2] = *(const unsigned*)&Ash[rm    ][kk + 8 + 2 * tg];
                a[mt][3] = *(const unsigned*)&Ash[rm + 8][kk + 8 + 2 * tg];
            }
#pragma unroll
            for (int nt = 0; nt < 8; nt++) {
                unsigned addr = bsh_base +
                    (unsigned)(((kk + klane) * 136 + wn + nt * 8) * 2);
                asm volatile(
                    "ldmatrix.sync.aligned.m8n8.x2.trans.shared.b16 {%0,%1}, [%2];"
                    : "=r"(b[nt][0]), "=r"(b[nt][1]) : "r"(addr));
            }
#pragma unroll
            for (int mt = 0; mt < 2; mt++)
#pragma unroll
                for (int nt = 0; nt < 8; nt++) {
                    asm volatile(
                        "mma.sync.aligned.m16n8k16.row.col.f32.f16.f16.f32 "
                        "{%0,%1,%2,%3}, {%4,%5,%6,%7}, {%8,%9}, {%0,%1,%2,%3};\n"
                        : "+f"(acc[mt][nt][0]), "+f"(acc[mt][nt][1]),
                          "+f"(acc[mt][nt][2]), "+f"(acc[mt][nt][3])
                        : "r"(a[mt][0]), "r"(a[mt][1]), "r"(a[mt][2]), "r"(a[mt][3]),
                          "r"(b[nt][0]), "r"(b[nt][1]));
                }
        }
        __syncthreads();
    }

#pragma unroll
    for (int mt = 0; mt < 2; mt++) {
        int r0 = brow + wm + mt * 16 + g;
        int r1 = r0 + 8;
#pragma unroll
        for (int nt = 0; nt < 8; nt++) {
            int cfull = bcol + wn + nt * 8 + 2 * tg;
            int c = cb + wn + nt * 8 + 2 * tg;
            float b0 = bias[cfull], b1 = bias[cfull + 1];
            float v00 = acc[mt][nt][0] + b0;
            float v01 = acc[mt][nt][1] + b1;
            float v10 = acc[mt][nt][2] + b0;
            float v11 = acc[mt][nt][3] + b1;
            if (act) {
                v00 = v00 / (1.f + __expf(-v00));
                v01 = v01 / (1.f + __expf(-v01));
                v10 = v10 / (1.f + __expf(-v10));
                v11 = v11 / (1.f + __expf(-v11));
            }
            if (r0 < M) *(float2*)(Cb + (size_t)r0 * ldc + c) = make_float2(v00, v01);
            if (r1 < M) *(float2*)(Cb + (size_t)r1 * ldc + c) = make_float2(v10, v11);
        }
    }
}

// ---------------- final GEMM (u @ W2 + bW2) fused with residual + LayerNorm2 (fp16) ----------------
__global__ void __launch_bounds__(256, 2)
kg_mma_ln(const float* __restrict__ A, const float* __restrict__ Bm,
          const float* __restrict__ h, float* __restrict__ Out,
          const float* __restrict__ bias,
          const float* __restrict__ g2, const float* __restrict__ bn2,
          int M, int K) {
    const int N = 128;
    __shared__ __half Ash[128][40];
    __shared__ __half Bsh[32][136];
    __shared__ float ssum[128][2];
    __shared__ float ssq [128][2];

    const int tid  = threadIdx.x;
    const int warp = tid >> 5;
    const int lane = tid & 31;
    const int wm   = (warp >> 1) * 32;
    const int wn   = (warp & 1) * 64;
    const int g    = lane >> 2;
    const int tg   = lane & 3;
    const int brow = blockIdx.y * 128;

    float acc[2][8][4];
#pragma unroll
    for (int i = 0; i < 2; i++)
#pragma unroll
        for (int j = 0; j < 8; j++)
#pragma unroll
            for (int q = 0; q < 4; q++) acc[i][j][q] = 0.f;

    const int arow   = tid >> 3;
    const int acol   = (tid & 7) * 4;
    const int brow_l = tid >> 5;
    const int bcol_l = (tid & 31) * 4;

    const unsigned bsh_base = smem_u32(&Bsh[0][0]);
    const int klane = lane & 15;

    for (int k0 = 0; k0 < K; k0 += 32) {
#pragma unroll
        for (int i = 0; i < 4; i++) {
            int r = arow + i * 32;
            int grow = brow + r;
            float4 v = (grow < M) ? *(const float4*)(A + (size_t)grow * K + k0 + acol)
                                  : make_float4(0.f, 0.f, 0.f, 0.f);
            ((__half2*)&Ash[r][acol])[0] = __floats2half2_rn(v.x, v.y);
            ((__half2*)&Ash[r][acol])[1] = __floats2half2_rn(v.z, v.w);
        }
#pragma unroll
        for (int i = 0; i < 4; i++) {
            int r = brow_l + i * 8;
            float4 v = *(const float4*)(Bm + (size_t)(k0 + r) * N + bcol_l);
            ((__half2*)&Bsh[r][bcol_l])[0] = __floats2half2_rn(v.x, v.y);
            ((__half2*)&Bsh[r][bcol_l])[1] = __floats2half2_rn(v.z, v.w);
        }
        __syncthreads();

#pragma unroll
        for (int ks = 0; ks < 2; ks++) {
            const int kk = ks * 16;
            unsigned a[2][4], b[8][2];
#pragma unroll
            for (int mt = 0; mt < 2; mt++) {
                int rm = wm + mt * 16 + g;
                a[mt][0] = *(const unsigned*)&Ash[rm    ][kk + 2 * tg];
                a[mt][1] = *(const unsigned*)&Ash[rm + 8][kk + 2 * tg];
                a[mt][2] = *(const unsigned*)&Ash[rm    ][kk + 8 + 2 * tg];
                a[mt][3] = *(const unsigned*)&Ash[rm + 8][kk + 8 + 2 * tg];
            }
#pragma unroll
            for (int nt = 0; nt < 8; nt++) {
                unsigned addr = bsh_base +
                    (unsigned)(((kk + klane) * 136 + wn + nt * 8) * 2);
                asm volatile(
                    "ldmatrix.sync.aligned.m8n8.x2.trans.shared.b16 {%0,%1}, [%2];"
                    : "=r"(b[nt][0]), "=r"(b[nt][1]) : "r"(addr));
            }
#pragma unroll
            for (int mt = 0; mt < 2; mt++)
#pragma unroll
                for (int nt = 0; nt < 8; nt++) {
                    asm volatile(
                        "mma.sync.aligned.m16n8k16.row.col.f32.f16.f16.f32 "
                        "{%0,%1,%2,%3}, {%4,%5,%6,%7}, {%8,%9}, {%0,%1,%2,%3};\n"
                        : "+f"(acc[mt][nt][0]), "+f"(acc[mt][nt][1]),
                          "+f"(acc[mt][nt][2]), "+f"(acc[mt][nt][3])
                        : "r"(a[mt][0]), "r"(a[mt][1]), "r"(a[mt][2]), "r"(a[mt][3]),
                          "r"(b[nt][0]), "r"(b[nt][1]));
                }
        }
        __syncthreads();
    }

    // ---- epilogue: vals = acc + bias + h; per-row LN ----
    float rs[2][2] = {{0.f, 0.f}, {0.f, 0.f}};
    float rq[2][2] = {{0.f, 0.f}, {0.f, 0.f}};
#pragma unroll
    for (int mt = 0; mt < 2; mt++) {
        int r0 = brow + wm + mt * 16 + g;
        int r1 = r0 + 8;
#pragma unroll
        for (int nt = 0; nt < 8; nt++) {
            int c = wn + nt * 8 + 2 * tg;
            float b0 = bias[c], b1 = bias[c + 1];
            float v00 = acc[mt][nt][0] + b0;
            float v01 = acc[mt][nt][1] + b1;
            float v10 = acc[mt][nt][2] + b0;
            float v11 = acc[mt][nt][3] + b1;
            if (r0 < M) {
                float2 hh = *(const float2*)(h + (size_t)r0 * 128 + c);
                v00 += hh.x; v01 += hh.y;
            }
            if (r1 < M) {
                float2 hh = *(const float2*)(h + (size_t)r1 * 128 + c);
                v10 += hh.x; v11 += hh.y;
            }
            acc[mt][nt][0] = v00; acc[mt][nt][1] = v01;
            acc[mt][nt][2] = v10; acc[mt][nt][3] = v11;
            rs[mt][0] += v00 + v01;
            rq[mt][0] += v00 * v00 + v01 * v01;
            rs[mt][1] += v10 + v11;
            rq[mt][1] += v10 * v10 + v11 * v11;
        }
    }
#pragma unroll
    for (int mt = 0; mt < 2; mt++)
#pragma unroll
        for (int hf = 0; hf < 2; hf++) {
            rs[mt][hf] += __shfl_xor_sync(0xffffffffu, rs[mt][hf], 1);
            rs[mt][hf] += __shfl_xor_sync(0xffffffffu, rs[mt][hf], 2);
            rq[mt][hf] += __shfl_xor_sync(0xffffffffu, rq[mt][hf], 1);
            rq[mt][hf] += __shfl_xor_sync(0xffffffffu, rq[mt][hf], 2);
        }
    if (tg == 0) {
#pragma unroll
        for (int mt = 0; mt < 2; mt++)
#pragma unroll
            for (int hf = 0; hf < 2; hf++) {
                int rl = wm + mt * 16 + hf * 8 + g;
                ssum[rl][wn >> 6] = rs[mt][hf];
                ssq [rl][wn >> 6] = rq[mt][hf];
            }
    }
    __syncthreads();

#pragma unroll
    for (int mt = 0; mt < 2; mt++) {
#pragma unroll
        for (int hf = 0; hf < 2; hf++) {
            int rl = wm + mt * 16 + hf * 8 + g;
            int rg = brow + rl;
            if (rg >= M) continue;
            float sm = ssum[rl][0] + ssum[rl][1];
            float sq = ssq [rl][0] + ssq [rl][1];
            float mu = sm * (1.f / 128.f);
            float var = sq * (1.f / 128.f) - mu * mu;
            float rstd = rsqrtf(var + 1e-5f);
#pragma unroll
            for (int nt = 0; nt < 8; nt++) {
                int c = wn + nt * 8 + 2 * tg;
                float va = acc[mt][nt][hf * 2 + 0];
                float vb = acc[mt][nt][hf * 2 + 1];
                float o0 = (va - mu) * rstd * g2[c]     + bn2[c];
                float o1 = (vb - mu) * rstd * g2[c + 1] + bn2[c + 1];
                *(float2*)(Out + (size_t)rg * 128 + c) = make_float2(o0, o1);
            }
        }
    }
}

// ---------------- launch ----------------
extern "C" void kernel_launch(void* const* d_in, const int* in_sizes, int n_in,
                              void* d_out, int out_size) {
    const float* x        = (const float*)d_in[0];
    const int*   ei       = (const int*)  d_in[1];
    const float* Wl       = (const float*)d_in[2];
    const float* bl       = (const float*)d_in[3];
    const float* Wr       = (const float*)d_in[4];
    const float* br       = (const float*)d_in[5];
    const float* att      = (const float*)d_in[6];
    const float* bias_gat = (const float*)d_in[7];
    const float* g1       = (const float*)d_in[8];
    const float* bn1      = (const float*)d_in[9];
    const float* W1       = (const float*)d_in[10];
    const float* bW1      = (const float*)d_in[11];
    const float* W2       = (const float*)d_in[12];
    const float* bW2      = (const float*)d_in[13];
    const float* g2       = (const float*)d_in[14];
    const float* bn2      = (const float*)d_in[15];
    float* out = (float*)d_out;

    const int n = in_sizes[0] / FDIM;      // 100000
    const int E = in_sizes[1] / 2;         // 1600000

    float *p_xl, *p_xr, *p_t, *p_u, *p_h, *p_wcat, *p_bcat;
    int *p_deg;
    cudaGetSymbolAddress((void**)&p_xl,   kg_xl);
    cudaGetSymbolAddress((void**)&p_xr,   kg_xr);
    cudaGetSymbolAddress((void**)&p_t,    kg_t);
    cudaGetSymbolAddress((void**)&p_u,    kg_u);
    cudaGetSymbolAddress((void**)&p_h,    kg_h);
    cudaGetSymbolAddress((void**)&p_wcat, kg_wcat);
    cudaGetSymbolAddress((void**)&p_bcat, kg_bcat);
    cudaGetSymbolAddress((void**)&p_deg,  kg_deg);

    const int scan_blocks = (n + 255) / 256;

    kg_prep<<<(FDIM * 256 + 255) / 256, 256>>>(Wl, Wr, bl, br);
    cudaMemsetAsync(p_deg, 0, (size_t)n * sizeof(int), 0);

    kg_hist<<<(E + 255) / 256, 256>>>(ei, E);
    kg_scan1<<<scan_blocks, 256>>>(n);
    kg_scan2<<<1, 1024>>>(scan_blocks);
    kg_scan3<<<scan_blocks, 256>>>(n);
    kg_scatter<<<(E + 255) / 256, 256>>>(ei, E);

    const int MB = (n + 127) / 128;

    // 1) [xl|xr] = x @ [Wl|Wr] + [bl|br]  (fp16 MMA, split outputs)
    kg_mma<<<dim3(2, MB), 256>>>(x, p_wcat, p_xl, p_xr, p_bcat, n, 256, 128, 128, 0);

    // 2) fused GAT gather + LN1
    kg_gather_ln<<<(n + 7) / 8, 256>>>(att, bias_gat, g1, bn1, n);

    // 3) u = silu(t @ W1 + bW1)  (fp16 MMA)
    kg_mma<<<dim3(4, MB), 256>>>(p_t, W1, p_u, nullptr, bW1, n, 512, 128, 512, 1);

    // 4) out = LN2(h + u @ W2 + bW2)  (fp16 MMA, fused residual + LN)
    kg_mma_ln<<<dim3(1, MB), 256>>>(p_u, W2, p_h, out, bW2, g2, bn2, n, 512);
}

// round 13
// speedup vs baseline: 1.6256x; 1.0908x over previous
#include <cuda_runtime.h>
#include <cuda_bf16.h>
#include <cuda_fp16.h>
#include <stdint.h>
#include <math.h>

#define NMAX 100000
#define EMAX 1600000
#define FDIM 128
#define FFDIM 512

// ---------------- scratch (static device globals; no allocation) ----------------
__device__ float kh_xl [(size_t)NMAX * FDIM];  // source-side transform (gathered)
__device__ float kh_xr [(size_t)NMAX * FDIM];  // target-side transform
__device__ float kh_h  [(size_t)NMAX * FDIM];  // GAT output (+bias), residual stream
__device__ float kh_t  [(size_t)NMAX * FDIM];  // LN1 output
__device__ float kh_u  [(size_t)NMAX * FFDIM]; // silu(t@W1+b)
__device__ float kh_wcat[FDIM * 256];          // [Wl | Wr] concatenated along cols
__device__ float kh_bcat[256];

// CSR build scratch
__device__ int kh_deg [NMAX];
__device__ int kh_off [NMAX];
__device__ int kh_cur [NMAX];
__device__ int kh_inc [NMAX];
__device__ int kh_bsum[1024];
__device__ int kh_srcs[EMAX];

// ---------------- weight concat prep ----------------
__global__ void kh_prep(const float* __restrict__ Wl, const float* __restrict__ Wr,
                        const float* __restrict__ bl, const float* __restrict__ br) {
    int i = blockIdx.x * blockDim.x + threadIdx.x;
    if (i < FDIM * 256) {
        int k = i >> 8, j = i & 255;
        kh_wcat[i] = (j < 128) ? Wl[k * 128 + j] : Wr[k * 128 + (j - 128)];
    }
    if (i < 256) kh_bcat[i] = (i < 128) ? bl[i] : br[i - 128];
}

// ---------------- CSR build ----------------
__global__ void kh_hist(const int* __restrict__ ei, int E_) {
    int i = blockIdx.x * blockDim.x + threadIdx.x;
    if (i < E_) atomicAdd(&kh_deg[ei[E_ + i]], 1);
}

__global__ void kh_scan1(int n) {
    __shared__ int sm[256];
    int t = threadIdx.x;
    int idx = blockIdx.x * 256 + t;
    int v = (idx < n) ? kh_deg[idx] : 0;
    sm[t] = v;
    __syncthreads();
#pragma unroll
    for (int o = 1; o < 256; o <<= 1) {
        int add = (t >= o) ? sm[t - o] : 0;
        __syncthreads();
        sm[t] += add;
        __syncthreads();
    }
    if (idx < n) kh_inc[idx] = sm[t];
    if (t == 255) kh_bsum[blockIdx.x] = sm[255];
}

__global__ void kh_scan2(int nblocks) {
    __shared__ int sm[1024];
    int t = threadIdx.x;
    sm[t] = (t < nblocks) ? kh_bsum[t] : 0;
    __syncthreads();
#pragma unroll
    for (int o = 1; o < 1024; o <<= 1) {
        int add = (t >= o) ? sm[t - o] : 0;
        __syncthreads();
        sm[t] += add;
        __syncthreads();
    }
    if (t < nblocks) kh_bsum[t] = sm[t];
}

__global__ void kh_scan3(int n) {
    int idx = blockIdx.x * blockDim.x + threadIdx.x;
    if (idx >= n) return;
    int b = idx >> 8;
    int prev = (b > 0) ? kh_bsum[b - 1] : 0;
    int excl = kh_inc[idx] - kh_deg[idx] + prev;
    kh_off[idx] = excl;
    kh_cur[idx] = excl;
}

__global__ void kh_scatter(const int* __restrict__ ei, int E_) {
    int i = blockIdx.x * blockDim.x + threadIdx.x;
    if (i >= E_) return;
    int dst = ei[E_ + i];
    int pos = atomicAdd(&kh_cur[dst], 1);
    kh_srcs[pos] = ei[i];
}

// ---------------- fused GAT gather + LayerNorm1 ----------------
__global__ void __launch_bounds__(256)
kh_gather_ln(const float* __restrict__ att, const float* __restrict__ bias,
             const float* __restrict__ g1, const float* __restrict__ bn1, int n) {
    int warp = (blockIdx.x * blockDim.x + threadIdx.x) >> 5;
    int lane = threadIdx.x & 31;
    if (warp >= n) return;

    const float4* xl4 = (const float4*)kh_xl;
    float4 xr = ((const float4*)kh_xr)[(size_t)warp * 32 + lane];
    float4 w  = ((const float4*)att)[lane];

    int start = kh_off[warp];
    int deg   = kh_deg[warp];

    float4 ws = make_float4(0.f, 0.f, 0.f, 0.f);
    float den = 0.f;

#define EDGE_STEP(a)                                                           \
    {                                                                          \
        float4 t;                                                              \
        t.x = a.x + xr.x; t.x = t.x > 0.f ? t.x : 0.2f * t.x;                  \
        t.y = a.y + xr.y; t.y = t.y > 0.f ? t.y : 0.2f * t.y;                  \
        t.z = a.z + xr.z; t.z = t.z > 0.f ? t.z : 0.2f * t.z;                  \
        t.w = a.w + xr.w; t.w = t.w > 0.f ? t.w : 0.2f * t.w;                  \
        float p = t.x * w.x + t.y * w.y + t.z * w.z + t.w * w.w;               \
        p += __shfl_xor_sync(0xffffffffu, p, 1);                               \
        p += __shfl_xor_sync(0xffffffffu, p, 2);                               \
        float ex = __expf(p);                                                  \
        den += ex;                                                             \
        ws.x += ex * a.x; ws.y += ex * a.y;                                    \
        ws.z += ex * a.z; ws.w += ex * a.w;                                    \
    }

    int j = 0;
    for (; j + 4 <= deg; j += 4) {
        int q0 = kh_srcs[start + j + 0];
        int q1 = kh_srcs[start + j + 1];
        int q2 = kh_srcs[start + j + 2];
        int q3 = kh_srcs[start + j + 3];
        float4 a0 = xl4[(size_t)q0 * 32 + lane];
        float4 a1 = xl4[(size_t)q1 * 32 + lane];
        float4 a2 = xl4[(size_t)q2 * 32 + lane];
        float4 a3 = xl4[(size_t)q3 * 32 + lane];
        EDGE_STEP(a0) EDGE_STEP(a1) EDGE_STEP(a2) EDGE_STEP(a3)
    }
    for (; j < deg; j++) {
        int q = kh_srcs[start + j];
        float4 a = xl4[(size_t)q * 32 + lane];
        EDGE_STEP(a)
    }
#undef EDGE_STEP

    float invd = (den > 0.f) ? (1.f / den) : 0.f;
    float4 bb = ((const float4*)bias)[lane];
    float4 o;
    o.x = ws.x * invd + bb.x;
    o.y = ws.y * invd + bb.y;
    o.z = ws.z * invd + bb.z;
    o.w = ws.w * invd + bb.w;
    ((float4*)(kh_h + (size_t)warp * 128))[lane] = o;

    // fused LayerNorm1 -> kh_t
    float sm = o.x + o.y + o.z + o.w;
    float sq = o.x * o.x + o.y * o.y + o.z * o.z + o.w * o.w;
#pragma unroll
    for (int of = 16; of; of >>= 1) {
        sm += __shfl_xor_sync(0xffffffffu, sm, of);
        sq += __shfl_xor_sync(0xffffffffu, sq, of);
    }
    float mu = sm * (1.f / 128.f);
    float var = sq * (1.f / 128.f) - mu * mu;
    float rstd = rsqrtf(var + 1e-5f);
    float4 gg = ((const float4*)g1)[lane];
    float4 b1 = ((const float4*)bn1)[lane];
    float4 t4;
    t4.x = (o.x - mu) * rstd * gg.x + b1.x;
    t4.y = (o.y - mu) * rstd * gg.y + b1.y;
    t4.z = (o.z - mu) * rstd * gg.z + b1.z;
    t4.w = (o.w - mu) * rstd * gg.w + b1.w;
    ((float4*)(kh_t + (size_t)warp * 128))[lane] = t4;
}

// ---------------- FP16 tensor-core GEMM, software-pipelined (fp32 accumulate) ----------------
__device__ __forceinline__ unsigned smem_u32(const void* p) {
    return (unsigned)__cvta_generic_to_shared(p);
}

__device__ __forceinline__ uint2 pack4h(float4 v) {
    __half2 h0 = __floats2half2_rn(v.x, v.y);
    __half2 h1 = __floats2half2_rn(v.z, v.w);
    uint2 r;
    r.x = *(unsigned*)&h0;
    r.y = *(unsigned*)&h1;
    return r;
}

// C[M,N] = A[M,K] @ B[K,N] + bias, optional silu. BM=128, BN=128, BK=32.
// If C2 != null: blocks with bcol>=128 write C2 at (bcol-128), row stride ldc.
__global__ void __launch_bounds__(256, 2)
kh_mma(const float* __restrict__ A, const float* __restrict__ Bm,
       float* __restrict__ C, float* __restrict__ C2,
       const float* __restrict__ bias,
       int M, int N, int K, int ldc, int act) {
    __shared__ __half Ash[128][40];
    __shared__ __half Bsh[32][136];

    const int tid  = threadIdx.x;
    const int warp = tid >> 5;
    const int lane = tid & 31;
    const int wm   = (warp >> 1) * 32;
    const int wn   = (warp & 1) * 64;
    const int g    = lane >> 2;
    const int tg   = lane & 3;
    const int brow = blockIdx.y * 128;
    const int bcol = blockIdx.x * 128;

    float* Cb = C;
    int cb = bcol;
    if (C2 && bcol >= 128) { Cb = C2; cb = bcol - 128; }

    float acc[2][8][4];
#pragma unroll
    for (int i = 0; i < 2; i++)
#pragma unroll
        for (int j = 0; j < 8; j++)
#pragma unroll
            for (int q = 0; q < 4; q++) acc[i][j][q] = 0.f;

    const int arow   = tid >> 3;
    const int acol   = (tid & 7) * 4;
    const int brow_l = tid >> 5;
    const int bcol_l = (tid & 31) * 4;

    const unsigned bsh_base = smem_u32(&Bsh[0][0]);
    const int klane = lane & 15;

    const bool a_ok = (brow + arow < M);  // conservative; rows arow+i*32 checked per load

    uint2 ast[4], bst[4];
    // prefetch k0 = 0
#pragma unroll
    for (int i = 0; i < 4; i++) {
        int grow = brow + arow + i * 32;
        float4 v = (grow < M) ? *(const float4*)(A + (size_t)grow * K + acol)
                              : make_float4(0.f, 0.f, 0.f, 0.f);
        ast[i] = pack4h(v);
    }
#pragma unroll
    for (int i = 0; i < 4; i++) {
        int r = brow_l + i * 8;
        float4 v = *(const float4*)(Bm + (size_t)r * N + bcol + bcol_l);
        bst[i] = pack4h(v);
    }

    for (int k0 = 0; k0 < K; k0 += 32) {
        // store staged tile
#pragma unroll
        for (int i = 0; i < 4; i++)
            *(uint2*)&Ash[arow + i * 32][acol] = ast[i];
#pragma unroll
        for (int i = 0; i < 4; i++)
            *(uint2*)&Bsh[brow_l + i * 8][bcol_l] = bst[i];
        __syncthreads();

        // prefetch next tile while MMA runs
        if (k0 + 32 < K) {
#pragma unroll
            for (int i = 0; i < 4; i++) {
                int grow = brow + arow + i * 32;
                float4 v = (grow < M) ? *(const float4*)(A + (size_t)grow * K + k0 + 32 + acol)
                                      : make_float4(0.f, 0.f, 0.f, 0.f);
                ast[i] = pack4h(v);
            }
#pragma unroll
            for (int i = 0; i < 4; i++) {
                int r = brow_l + i * 8;
                float4 v = *(const float4*)(Bm + (size_t)(k0 + 32 + r) * N + bcol + bcol_l);
                bst[i] = pack4h(v);
            }
        }

#pragma unroll
        for (int ks = 0; ks < 2; ks++) {
            const int kk = ks * 16;
            unsigned a[2][4], b[8][2];
#pragma unroll
            for (int mt = 0; mt < 2; mt++) {
                int rm = wm + mt * 16 + g;
                a[mt][0] = *(const unsigned*)&Ash[rm    ][kk + 2 * tg];
                a[mt][1] = *(const unsigned*)&Ash[rm + 8][kk + 2 * tg];
                a[mt][2] = *(const unsigned*)&Ash[rm    ][kk + 8 + 2 * tg];
                a[mt][3] = *(const unsigned*)&Ash[rm + 8][kk + 8 + 2 * tg];
            }
#pragma unroll
            for (int nt = 0; nt < 8; nt++) {
                unsigned addr = bsh_base +
                    (unsigned)(((kk + klane) * 136 + wn + nt * 8) * 2);
                asm volatile(
                    "ldmatrix.sync.aligned.m8n8.x2.trans.shared.b16 {%0,%1}, [%2];"
                    : "=r"(b[nt][0]), "=r"(b[nt][1]) : "r"(addr));
            }
#pragma unroll
            for (int mt = 0; mt < 2; mt++)
#pragma unroll
                for (int nt = 0; nt < 8; nt++) {
                    asm volatile(
                        "mma.sync.aligned.m16n8k16.row.col.f32.f16.f16.f32 "
                        "{%0,%1,%2,%3}, {%4,%5,%6,%7}, {%8,%9}, {%0,%1,%2,%3};\n"
                        : "+f"(acc[mt][nt][0]), "+f"(acc[mt][nt][1]),
                          "+f"(acc[mt][nt][2]), "+f"(acc[mt][nt][3])
                        : "r"(a[mt][0]), "r"(a[mt][1]), "r"(a[mt][2]), "r"(a[mt][3]),
                          "r"(b[nt][0]), "r"(b[nt][1]));
                }
        }
        __syncthreads();
    }
    (void)a_ok;

#pragma unroll
    for (int mt = 0; mt < 2; mt++) {
        int r0 = brow + wm + mt * 16 + g;
        int r1 = r0 + 8;
#pragma unroll
        for (int nt = 0; nt < 8; nt++) {
            int cfull = bcol + wn + nt * 8 + 2 * tg;
            int c = cb + wn + nt * 8 + 2 * tg;
            float b0 = bias[cfull], b1 = bias[cfull + 1];
            float v00 = acc[mt][nt][0] + b0;
            float v01 = acc[mt][nt][1] + b1;
            float v10 = acc[mt][nt][2] + b0;
            float v11 = acc[mt][nt][3] + b1;
            if (act) {
                v00 = v00 / (1.f + __expf(-v00));
                v01 = v01 / (1.f + __expf(-v01));
                v10 = v10 / (1.f + __expf(-v10));
                v11 = v11 / (1.f + __expf(-v11));
            }
            if (r0 < M) *(float2*)(Cb + (size_t)r0 * ldc + c) = make_float2(v00, v01);
            if (r1 < M) *(float2*)(Cb + (size_t)r1 * ldc + c) = make_float2(v10, v11);
        }
    }
}

// ---------------- final GEMM (u @ W2 + bW2) fused with residual + LayerNorm2, pipelined ----------------
__global__ void __launch_bounds__(256, 2)
kh_mma_ln(const float* __restrict__ A, const float* __restrict__ Bm,
          const float* __restrict__ h, float* __restrict__ Out,
          const float* __restrict__ bias,
          const float* __restrict__ g2, const float* __restrict__ bn2,
          int M, int K) {
    const int N = 128;
    __shared__ __half Ash[128][40];
    __shared__ __half Bsh[32][136];
    __shared__ float ssum[128][2];
    __shared__ float ssq [128][2];

    const int tid  = threadIdx.x;
    const int warp = tid >> 5;
    const int lane = tid & 31;
    const int wm   = (warp >> 1) * 32;
    const int wn   = (warp & 1) * 64;
    const int g    = lane >> 2;
    const int tg   = lane & 3;
    const int brow = blockIdx.y * 128;

    float acc[2][8][4];
#pragma unroll
    for (int i = 0; i < 2; i++)
#pragma unroll
        for (int j = 0; j < 8; j++)
#pragma unroll
            for (int q = 0; q < 4; q++) acc[i][j][q] = 0.f;

    const int arow   = tid >> 3;
    const int acol   = (tid & 7) * 4;
    const int brow_l = tid >> 5;
    const int bcol_l = (tid & 31) * 4;

    const unsigned bsh_base = smem_u32(&Bsh[0][0]);
    const int klane = lane & 15;

    uint2 ast[4], bst[4];
#pragma unroll
    for (int i = 0; i < 4; i++) {
        int grow = brow + arow + i * 32;
        float4 v = (grow < M) ? *(const float4*)(A + (size_t)grow * K + acol)
                              : make_float4(0.f, 0.f, 0.f, 0.f);
        ast[i] = pack4h(v);
    }
#pragma unroll
    for (int i = 0; i < 4; i++) {
        int r = brow_l + i * 8;
        float4 v = *(const float4*)(Bm + (size_t)r * N + bcol_l);
        bst[i] = pack4h(v);
    }

    for (int k0 = 0; k0 < K; k0 += 32) {
#pragma unroll
        for (int i = 0; i < 4; i++)
            *(uint2*)&Ash[arow + i * 32][acol] = ast[i];
#pragma unroll
        for (int i = 0; i < 4; i++)
            *(uint2*)&Bsh[brow_l + i * 8][bcol_l] = bst[i];
        __syncthreads();

        if (k0 + 32 < K) {
#pragma unroll
            for (int i = 0; i < 4; i++) {
                int grow = brow + arow + i * 32;
                float4 v = (grow < M) ? *(const float4*)(A + (size_t)grow * K + k0 + 32 + acol)
                                      : make_float4(0.f, 0.f, 0.f, 0.f);
                ast[i] = pack4h(v);
            }
#pragma unroll
            for (int i = 0; i < 4; i++) {
                int r = brow_l + i * 8;
                float4 v = *(const float4*)(Bm + (size_t)(k0 + 32 + r) * N + bcol_l);
                bst[i] = pack4h(v);
            }
        }

#pragma unroll
        for (int ks = 0; ks < 2; ks++) {
            const int kk = ks * 16;
            unsigned a[2][4], b[8][2];
#pragma unroll
            for (int mt = 0; mt < 2; mt++) {
                int rm = wm + mt * 16 + g;
                a[mt][0] = *(const unsigned*)&Ash[rm    ][kk + 2 * tg];
                a[mt][1] = *(const unsigned*)&Ash[rm + 8][kk + 2 * tg];
                a[mt][2] = *(const unsigned*)&Ash[rm    ][kk + 8 + 2 * tg];
                a[mt][3] = *(const unsigned*)&Ash[rm + 8][kk + 8 + 2 * tg];
            }
#pragma unroll
            for (int nt = 0; nt < 8; nt++) {
                unsigned addr = bsh_base +
                    (unsigned)(((kk + klane) * 136 + wn + nt * 8) * 2);
                asm volatile(
                    "ldmatrix.sync.aligned.m8n8.x2.trans.shared.b16 {%0,%1}, [%2];"
                    : "=r"(b[nt][0]), "=r"(b[nt][1]) : "r"(addr));
            }
#pragma unroll
            for (int mt = 0; mt < 2; mt++)
#pragma unroll
                for (int nt = 0; nt < 8; nt++) {
                    asm volatile(
                        "mma.sync.aligned.m16n8k16.row.col.f32.f16.f16.f32 "
                        "{%0,%1,%2,%3}, {%4,%5,%6,%7}, {%8,%9}, {%0,%1,%2,%3};\n"
                        : "+f"(acc[mt][nt][0]), "+f"(acc[mt][nt][1]),
                          "+f"(acc[mt][nt][2]), "+f"(acc[mt][nt][3])
                        : "r"(a[mt][0]), "r"(a[mt][1]), "r"(a[mt][2]), "r"(a[mt][3]),
                          "r"(b[nt][0]), "r"(b[nt][1]));
                }
        }
        __syncthreads();
    }

    // ---- epilogue: vals = acc + bias + h; per-row LN ----
    float rs[2][2] = {{0.f, 0.f}, {0.f, 0.f}};
    float rq[2][2] = {{0.f, 0.f}, {0.f, 0.f}};
#pragma unroll
    for (int mt = 0; mt < 2; mt++) {
        int r0 = brow + wm + mt * 16 + g;
        int r1 = r0 + 8;
#pragma unroll
        for (int nt = 0; nt < 8; nt++) {
            int c = wn + nt * 8 + 2 * tg;
            float b0 = bias[c], b1 = bias[c + 1];
            float v00 = acc[mt][nt][0] + b0;
            float v01 = acc[mt][nt][1] + b1;
            float v10 = acc[mt][nt][2] + b0;
            float v11 = acc[mt][nt][3] + b1;
            if (r0 < M) {
                float2 hh = *(const float2*)(h + (size_t)r0 * 128 + c);
                v00 += hh.x; v01 += hh.y;
            }
            if (r1 < M) {
                float2 hh = *(const float2*)(h + (size_t)r1 * 128 + c);
                v10 += hh.x; v11 += hh.y;
            }
            acc[mt][nt][0] = v00; acc[mt][nt][1] = v01;
            acc[mt][nt][2] = v10; acc[mt][nt][3] = v11;
            rs[mt][0] += v00 + v01;
            rq[mt][0] += v00 * v00 + v01 * v01;
            rs[mt][1] += v10 + v11;
            rq[mt][1] += v10 * v10 + v11 * v11;
        }
    }
#pragma unroll
    for (int mt = 0; mt < 2; mt++)
#pragma unroll
        for (int hf = 0; hf < 2; hf++) {
            rs[mt][hf] += __shfl_xor_sync(0xffffffffu, rs[mt][hf], 1);
            rs[mt][hf] += __shfl_xor_sync(0xffffffffu, rs[mt][hf], 2);
            rq[mt][hf] += __shfl_xor_sync(0xffffffffu, rq[mt][hf], 1);
            rq[mt][hf] += __shfl_xor_sync(0xffffffffu, rq[mt][hf], 2);
        }
    if (tg == 0) {
#pragma unroll
        for (int mt = 0; mt < 2; mt++)
#pragma unroll
            for (int hf = 0; hf < 2; hf++) {
                int rl = wm + mt * 16 + hf * 8 + g;
                ssum[rl][wn >> 6] = rs[mt][hf];
                ssq [rl][wn >> 6] = rq[mt][hf];
            }
    }
    __syncthreads();

#pragma unroll
    for (int mt = 0; mt < 2; mt++) {
#pragma unroll
        for (int hf = 0; hf < 2; hf++) {
            int rl = wm + mt * 16 + hf * 8 + g;
            int rg = brow + rl;
            if (rg >= M) continue;
            float sm = ssum[rl][0] + ssum[rl][1];
            float sq = ssq [rl][0] + ssq [rl][1];
            float mu = sm * (1.f / 128.f);
            float var = sq * (1.f / 128.f) - mu * mu;
            float rstd = rsqrtf(var + 1e-5f);
#pragma unroll
            for (int nt = 0; nt < 8; nt++) {
                int c = wn + nt * 8 + 2 * tg;
                float va = acc[mt][nt][hf * 2 + 0];
                float vb = acc[mt][nt][hf * 2 + 1];
                float o0 = (va - mu) * rstd * g2[c]     + bn2[c];
                float o1 = (vb - mu) * rstd * g2[c + 1] + bn2[c + 1];
                *(float2*)(Out + (size_t)rg * 128 + c) = make_float2(o0, o1);
            }
        }
    }
}

// ---------------- launch ----------------
extern "C" void kernel_launch(void* const* d_in, const int* in_sizes, int n_in,
                              void* d_out, int out_size) {
    const float* x        = (const float*)d_in[0];
    const int*   ei       = (const int*)  d_in[1];
    const float* Wl       = (const float*)d_in[2];
    const float* bl       = (const float*)d_in[3];
    const float* Wr       = (const float*)d_in[4];
    const float* br       = (const float*)d_in[5];
    const float* att      = (const float*)d_in[6];
    const float* bias_gat = (const float*)d_in[7];
    const float* g1       = (const float*)d_in[8];
    const float* bn1      = (const float*)d_in[9];
    const float* W1       = (const float*)d_in[10];
    const float* bW1      = (const float*)d_in[11];
    const float* W2       = (const float*)d_in[12];
    const float* bW2      = (const float*)d_in[13];
    const float* g2       = (const float*)d_in[14];
    const float* bn2      = (const float*)d_in[15];
    float* out = (float*)d_out;

    const int n = in_sizes[0] / FDIM;      // 100000
    const int E = in_sizes[1] / 2;         // 1600000

    float *p_xl, *p_xr, *p_t, *p_u, *p_h, *p_wcat, *p_bcat;
    int *p_deg;
    cudaGetSymbolAddress((void**)&p_xl,   kh_xl);
    cudaGetSymbolAddress((void**)&p_xr,   kh_xr);
    cudaGetSymbolAddress((void**)&p_t,    kh_t);
    cudaGetSymbolAddress((void**)&p_u,    kh_u);
    cudaGetSymbolAddress((void**)&p_h,    kh_h);
    cudaGetSymbolAddress((void**)&p_wcat, kh_wcat);
    cudaGetSymbolAddress((void**)&p_bcat, kh_bcat);
    cudaGetSymbolAddress((void**)&p_deg,  kh_deg);

    const int scan_blocks = (n + 255) / 256;

    kh_prep<<<(FDIM * 256 + 255) / 256, 256>>>(Wl, Wr, bl, br);
    cudaMemsetAsync(p_deg, 0, (size_t)n * sizeof(int), 0);

    kh_hist<<<(E + 255) / 256, 256>>>(ei, E);
    kh_scan1<<<scan_blocks, 256>>>(n);
    kh_scan2<<<1, 1024>>>(scan_blocks);
    kh_scan3<<<scan_blocks, 256>>>(n);
    kh_scatter<<<(E + 255) / 256, 256>>>(ei, E);

    const int MB = (n + 127) / 128;

    // 1) [xl|xr] = x @ [Wl|Wr] + [bl|br]  (fp16 MMA, pipelined, split outputs)
    kh_mma<<<dim3(2, MB), 256>>>(x, p_wcat, p_xl, p_xr, p_bcat, n, 256, 128, 128, 0);

    // 2) fused GAT gather + LN1
    kh_gather_ln<<<(n + 7) / 8, 256>>>(att, bias_gat, g1, bn1, n);

    // 3) u = silu(t @ W1 + bW1)  (fp16 MMA, pipelined)
    kh_mma<<<dim3(4, MB), 256>>>(p_t, W1, p_u, nullptr, bW1, n, 512, 128, 512, 1);

    // 4) out = LN2(h + u @ W2 + bW2)  (fp16 MMA, pipelined, fused residual + LN)
    kh_mma_ln<<<dim3(1, MB), 256>>>(p_u, W2, p_h, out, bW2, g2, bn2, n, 512);
}